// round 5
// baseline (speedup 1.0000x reference)
#include <cuda_runtime.h>
#include <math_constants.h>

// Problem constants (fixed by the dataset)
#define Bb 4
#define Hh 512
#define Ww 512
#define Cc 32
#define HO 256
#define WO 256
#define HP 514                   // padded height (1-pixel halo)
#define WP 514                   // padded width
#define NPAD (Bb*HP*WP)

// Per-pixel slot over the PADDED grid, generation-tagged:
//   slot = ((long long)gen << 32) | (point_index + 1)
// A slot is live only if its high word equals the current generation, so stale
// entries from previous calls/replays are invalid without any clearing pass.
__device__ long long g_slot[NPAD];   // zero-init at load; gen starts at 0, first call uses gen=1
__device__ int       g_gen;

__global__ void bump_gen_kernel() { g_gen = g_gen + 1; }

// One thread per point: plain 8B store — coords are unique, no atomics.
__global__ void scatter_kernel(const int* __restrict__ coors, int n_pts) {
    int n = blockIdx.x * blockDim.x + threadIdx.x;
    if (n >= n_pts) return;
    long long tag = ((long long)g_gen) << 32;
    int b = coors[n * 3 + 0];
    int y = coors[n * 3 + 1];
    int x = coors[n * 3 + 2];
    g_slot[(b * HP + (y + 1)) * WP + (x + 1)] = tag | (unsigned)(n + 1);
}

// 8 threads per PAIR of horizontally-adjacent output pixels (4 channels each as
// float4). 3 rows x 5 cols of slots, loaded as 2x longlong2 + 1 scalar per row
// (16B-aligned), validated against the current generation.
__global__ void __launch_bounds__(256) pool_kernel(const float* __restrict__ feat,
                                                   float* __restrict__ out) {
    int t      = blockIdx.x * blockDim.x + threadIdx.x;
    int pairId = t >> 3;              // which pixel pair (exact grid)
    int lane8  = t & 7;               // channel chunk: 4 floats

    int xp = pairId & (WO / 2 - 1);   // pair x: 0..127
    int yo = (pairId >> 7) & (HO - 1);
    int b  = pairId >> 15;

    int gen = g_gen;

    // window top-left of left pixel in padded coords: (2*yo, 4*xp)
    const long long* __restrict__ sp = g_slot + ((b * HP + 2 * yo) * WP + 4 * xp);

    // 9 vectorized probe loads covering 3 rows x 5 cols
    longlong2 r0a = *reinterpret_cast<const longlong2*>(sp);
    longlong2 r0b = *reinterpret_cast<const longlong2*>(sp + 2);
    long long r0e = sp[4];
    longlong2 r1a = *reinterpret_cast<const longlong2*>(sp + WP);
    longlong2 r1b = *reinterpret_cast<const longlong2*>(sp + WP + 2);
    long long r1e = sp[WP + 4];
    longlong2 r2a = *reinterpret_cast<const longlong2*>(sp + 2 * WP);
    longlong2 r2b = *reinterpret_cast<const longlong2*>(sp + 2 * WP + 2);
    long long r2e = sp[2 * WP + 4];

    #define DEC(S) ( ((int)((S) >> 32) == gen) ? (int)(S) : 0 )
    int r0c0 = DEC(r0a.x), r0c1 = DEC(r0a.y), r0c2 = DEC(r0b.x), r0c3 = DEC(r0b.y), r0c4 = DEC(r0e);
    int r1c0 = DEC(r1a.x), r1c1 = DEC(r1a.y), r1c2 = DEC(r1b.x), r1c3 = DEC(r1b.y), r1c4 = DEC(r1e);
    int r2c0 = DEC(r2a.x), r2c1 = DEC(r2a.y), r2c2 = DEC(r2b.x), r2c3 = DEC(r2b.y), r2c4 = DEC(r2e);
    #undef DEC

    int anyA = r0c0 | r0c1 | r0c2 | r1c0 | r1c1 | r1c2 | r2c0 | r2c1 | r2c2;
    int anyB = r0c2 | r0c3 | r0c4 | r1c2 | r1c3 | r1c4 | r2c2 | r2c3 | r2c4;

    const float4* __restrict__ f4 = reinterpret_cast<const float4*>(feat);
    float4 accA = make_float4(-CUDART_INF_F, -CUDART_INF_F, -CUDART_INF_F, -CUDART_INF_F);
    float4 accB = accA;

    #define MAX4(A, V) { A.x = fmaxf(A.x, V.x); A.y = fmaxf(A.y, V.y); \
                         A.z = fmaxf(A.z, V.z); A.w = fmaxf(A.w, V.w); }
    #define GA(S)  if (S) { float4 v = f4[(size_t)((S) - 1) * 8 + lane8]; MAX4(accA, v) }
    #define GB(S)  if (S) { float4 v = f4[(size_t)((S) - 1) * 8 + lane8]; MAX4(accB, v) }
    #define GAB(S) if (S) { float4 v = f4[(size_t)((S) - 1) * 8 + lane8]; MAX4(accA, v) MAX4(accB, v) }

    GA(r0c0) GA(r0c1) GAB(r0c2) GB(r0c3) GB(r0c4)
    GA(r1c0) GA(r1c1) GAB(r1c2) GB(r1c3) GB(r1c4)
    GA(r2c0) GA(r2c1) GAB(r2c2) GB(r2c3) GB(r2c4)

    #undef GA
    #undef GB
    #undef GAB
    #undef MAX4

    float4 zero = make_float4(0.f, 0.f, 0.f, 0.f);
    float4 oA = anyA ? accA : zero;
    float4 oB = anyB ? accB : zero;

    float4* __restrict__ o4 = reinterpret_cast<float4*>(out);
    size_t obase = (size_t)pairId * 16 + lane8;   // pixel 2*pairId
    o4[obase]     = oA;
    o4[obase + 8] = oB;
}

extern "C" void kernel_launch(void* const* d_in, const int* in_sizes, int n_in,
                              void* d_out, int out_size) {
    const float* feat  = (const float*)d_in[0];
    const int*   coors = (const int*)d_in[1];
    (void)n_in; (void)out_size;

    int n_pts = in_sizes[0] / Cc;   // 300000

    // 1) new generation — invalidates all existing slot entries
    bump_gen_kernel<<<1, 1>>>();

    // 2) scatter generation-tagged point indices
    scatter_kernel<<<(n_pts + 255) / 256, 256>>>(coors, n_pts);

    // 3) pair-wise 3x3/s2 max-pool, gathering features from the input array
    {
        int total = Bb * HO * (WO / 2) * 8;   // 1,048,576 threads
        pool_kernel<<<total / 256, 256>>>(feat, (float*)d_out);
    }
}